// round 1
// baseline (speedup 1.0000x reference)
#include <cuda_runtime.h>

#define N_TOK 4096
#define CH    256
#define NHD   4
#define DH    64
#define BATCH 2
#define BHN   8   // BATCH * NHD

// Scratch (static device globals; no allocation in kernel_launch)
__device__ float g_q [BHN * DH * N_TOK];     // [bh][d][n]
__device__ float g_k [BHN * DH * N_TOK];     // [bh][d][n]
__device__ float g_vt[BHN * N_TOK * DH];     // [bh][n][d]  (V transposed)
__device__ float g_y [BATCH * CH * N_TOK];   // [b][h*D+d][n]

// ---------------------------------------------------------------------------
// Kernel 1: QKV projection.  qkv[b,h,dd,n] = sum_c x[b,c,n] * w_embed[h,dd,c] + b
// grid (N/64, 3, BHN); part = blockIdx.y selects q/k/v (dd block of 64).
// ---------------------------------------------------------------------------
__global__ __launch_bounds__(256) void qkv_kernel(const float* __restrict__ x,
                                                  const float* __restrict__ w_embed,
                                                  const float* __restrict__ b_embed) {
    __shared__ float Ws[16][68];   // [c][dd]
    __shared__ float Xs[16][68];   // [c][n]
    const int bh = blockIdx.z, b = bh >> 2, h = bh & 3;
    const int part = blockIdx.y;
    const int n0 = blockIdx.x * 64;
    const int t = threadIdx.x, tx = t & 15, ty = t >> 4;
    const float* W = w_embed + (size_t)(h * 192 + part * 64) * 256;
    const float* X = x + (size_t)b * CH * N_TOK + n0;

    float acc[4][4] = {};
    for (int c0 = 0; c0 < 256; c0 += 16) {
        {   // load W tile transposed: Ws[cc][dd] = W[dd][c0+cc]
            const int dd = t >> 2, cc = (t & 3) << 2;
            float4 w4 = *(const float4*)(W + (size_t)dd * 256 + c0 + cc);
            Ws[cc + 0][dd] = w4.x; Ws[cc + 1][dd] = w4.y;
            Ws[cc + 2][dd] = w4.z; Ws[cc + 3][dd] = w4.w;
        }
        {   // load X tile: Xs[cc][n]
            const int cc = t >> 4, nn = (t & 15) << 2;
            *(float4*)&Xs[cc][nn] = *(const float4*)(X + (size_t)(c0 + cc) * N_TOK + nn);
        }
        __syncthreads();
        #pragma unroll
        for (int cc = 0; cc < 16; cc++) {
            float av[4], bv[4];
            *(float4*)av = *(const float4*)&Ws[cc][ty * 4];
            *(float4*)bv = *(const float4*)&Xs[cc][tx * 4];
            #pragma unroll
            for (int i = 0; i < 4; i++)
                #pragma unroll
                for (int j = 0; j < 4; j++)
                    acc[i][j] = fmaf(av[i], bv[j], acc[i][j]);
        }
        __syncthreads();
    }

    const float* bias = b_embed + h * 192 + part * 64 + ty * 4;
    float bi[4] = { bias[0], bias[1], bias[2], bias[3] };

    if (part == 2) {
        // store V transposed: g_vt[bh][n][d]
        float* dst = g_vt + ((size_t)bh * N_TOK + n0 + tx * 4) * DH + ty * 4;
        #pragma unroll
        for (int j = 0; j < 4; j++) {
            float4 v = make_float4(acc[0][j] + bi[0], acc[1][j] + bi[1],
                                   acc[2][j] + bi[2], acc[3][j] + bi[3]);
            *(float4*)(dst + (size_t)j * DH) = v;
        }
    } else {
        float* base = (part == 0 ? g_q : g_k) + (size_t)bh * DH * N_TOK;
        #pragma unroll
        for (int i = 0; i < 4; i++) {
            float4 v = make_float4(acc[i][0] + bi[i], acc[i][1] + bi[i],
                                   acc[i][2] + bi[i], acc[i][3] + bi[i]);
            *(float4*)(base + (size_t)(ty * 4 + i) * N_TOK + n0 + tx * 4) = v;
        }
    }
}

// ---------------------------------------------------------------------------
// Kernel 2: flash attention.  One block = one (bh, 64-query tile).
// S[i][j] = sum_d Qs[d][i]*Ks[d][j]; online softmax; Y[d][i] += P[i][j]*V[d][j].
// Thread grid 16(ty: i/d-groups) x 16(tx: j/i-groups), 4x4 micro-tiles.
// Row softmax reductions stay within 16 consecutive lanes -> shfl_xor.
// ---------------------------------------------------------------------------
__global__ __launch_bounds__(256, 3) void attn_kernel() {
    extern __shared__ float sm[];
    float* Qs   = sm;            // [64][64] [d][i] (pre-scaled)
    float* Ks   = sm + 4096;     // [64][64] [d][j]
    float* Vt   = sm + 8192;     // [64][64] [j][d]
    float* Ps   = sm + 12288;    // [64][64] [j][i], XOR-swizzled 4-float groups
    float* sm_m = sm + 16384;    // [64] running row max
    float* sm_l = sm_m + 64;     // [64] running row sum
    float* sm_a = sm_l + 64;     // [64] per-row rescale alpha

    const int bh = blockIdx.y;
    const int i0 = blockIdx.x * 64;
    const int t = threadIdx.x, tx = t & 15, ty = t >> 4;
    const float* q  = g_q  + (size_t)bh * DH * N_TOK;
    const float* k  = g_k  + (size_t)bh * DH * N_TOK;
    const float* vt = g_vt + (size_t)bh * N_TOK * DH;

    #pragma unroll
    for (int r = 0; r < 4; r++) {
        int e = r * 256 + t;
        int d = e >> 4, i = (e & 15) << 2;
        float4 v = *(const float4*)(q + (size_t)d * N_TOK + i0 + i);
        v.x *= 0.125f; v.y *= 0.125f; v.z *= 0.125f; v.w *= 0.125f;  // D^-0.5
        *(float4*)&Qs[d * 64 + i] = v;
    }
    if (t < 64) { sm_m[t] = -3.0e38f; sm_l[t] = 0.0f; }

    float yacc[4][4] = {};   // [dd][ii]: d = ty*4+dd, i = tx*4+ii

    for (int j0 = 0; j0 < N_TOK; j0 += 64) {
        __syncthreads();   // previous iteration's Ks/Vt/Ps reads done
        #pragma unroll
        for (int r = 0; r < 4; r++) {
            int e = r * 256 + t;
            int d = e >> 4, j = (e & 15) << 2;
            *(float4*)&Ks[d * 64 + j] = *(const float4*)(k + (size_t)d * N_TOK + j0 + j);
            int jr = e >> 4, dr = (e & 15) << 2;
            *(float4*)&Vt[jr * 64 + dr] = *(const float4*)(vt + (size_t)(j0 + jr) * DH + dr);
        }
        __syncthreads();

        // ---- S = Q^T K (i = ty*4+ii, j = tx*4+jj) ----
        float s[4][4] = {};
        #pragma unroll 16
        for (int d = 0; d < 64; d++) {
            float qv[4], kv[4];
            *(float4*)qv = *(const float4*)&Qs[d * 64 + ty * 4];
            *(float4*)kv = *(const float4*)&Ks[d * 64 + tx * 4];
            #pragma unroll
            for (int i = 0; i < 4; i++)
                #pragma unroll
                for (int j = 0; j < 4; j++)
                    s[i][j] = fmaf(qv[i], kv[j], s[i][j]);
        }

        // ---- online softmax ----
        float mnew[4], al[4], rs[4];
        #pragma unroll
        for (int i = 0; i < 4; i++) {
            float rm = fmaxf(fmaxf(s[i][0], s[i][1]), fmaxf(s[i][2], s[i][3]));
            #pragma unroll
            for (int off = 1; off < 16; off <<= 1)
                rm = fmaxf(rm, __shfl_xor_sync(0xffffffffu, rm, off));
            float mo = sm_m[ty * 4 + i];
            mnew[i] = fmaxf(mo, rm);
            al[i] = __expf(mo - mnew[i]);
            float sum = 0.0f;
            #pragma unroll
            for (int j = 0; j < 4; j++) {
                float p = __expf(s[i][j] - mnew[i]);
                s[i][j] = p;
                sum += p;
            }
            #pragma unroll
            for (int off = 1; off < 16; off <<= 1)
                sum += __shfl_xor_sync(0xffffffffu, sum, off);
            rs[i] = sum;
        }
        if (tx == 0) {
            #pragma unroll
            for (int i = 0; i < 4; i++) {
                int r = ty * 4 + i;
                sm_m[r] = mnew[i];
                sm_a[r] = al[i];
                sm_l[r] = sm_l[r] * al[i] + rs[i];
            }
        }
        // ---- store P transposed [j][i], XOR swizzle on 4-float groups ----
        #pragma unroll
        for (int j = 0; j < 4; j++) {
            int row = tx * 4 + j;
            int grp = ty ^ (row & 15);
            *(float4*)&Ps[row * 64 + grp * 4] =
                make_float4(s[0][j], s[1][j], s[2][j], s[3][j]);
        }
        __syncthreads();

        // ---- Y update: Y[d][i] = alpha[i]*Y + sum_j V[d][j]*P[i][j] ----
        float a4[4];
        #pragma unroll
        for (int i = 0; i < 4; i++) a4[i] = sm_a[tx * 4 + i];
        #pragma unroll
        for (int d = 0; d < 4; d++)
            #pragma unroll
            for (int i = 0; i < 4; i++)
                yacc[d][i] *= a4[i];
        #pragma unroll 16
        for (int j = 0; j < 64; j++) {
            float vv[4], pv[4];
            *(float4*)vv = *(const float4*)&Vt[j * 64 + ty * 4];
            int grp = tx ^ (j & 15);
            *(float4*)pv = *(const float4*)&Ps[j * 64 + grp * 4];
            #pragma unroll
            for (int d = 0; d < 4; d++)
                #pragma unroll
                for (int i = 0; i < 4; i++)
                    yacc[d][i] = fmaf(vv[d], pv[i], yacc[d][i]);
        }
    }

    float linv[4];
    #pragma unroll
    for (int i = 0; i < 4; i++) linv[i] = 1.0f / sm_l[tx * 4 + i];
    const int b = bh >> 2, h = bh & 3;
    float* ydst = g_y + ((size_t)b * CH + h * DH + ty * 4) * N_TOK + i0 + tx * 4;
    #pragma unroll
    for (int d = 0; d < 4; d++) {
        float4 v = make_float4(yacc[d][0] * linv[0], yacc[d][1] * linv[1],
                               yacc[d][2] * linv[2], yacc[d][3] * linv[3]);
        *(float4*)(ydst + (size_t)d * N_TOK) = v;
    }
}

// ---------------------------------------------------------------------------
// Kernel 3: output projection + bias + residual.
// out[b,c,n] = sum_k y[b,k,n] * w_out[k,c] + b_out[c] + x[b,c,n]
// ---------------------------------------------------------------------------
__global__ __launch_bounds__(256) void proj_kernel(const float* __restrict__ x,
                                                   const float* __restrict__ w_out,
                                                   const float* __restrict__ b_out,
                                                   float* __restrict__ out) {
    __shared__ float Ws[16][68];  // [kk][c]
    __shared__ float Ys[16][68];  // [kk][n]
    const int b  = blockIdx.z;
    const int c0 = blockIdx.y * 64;
    const int n0 = blockIdx.x * 64;
    const int t = threadIdx.x, tx = t & 15, ty = t >> 4;
    const float* Y = g_y + (size_t)b * CH * N_TOK;

    float acc[4][4] = {};
    for (int k0 = 0; k0 < 256; k0 += 16) {
        {
            const int kk = t >> 4, cc = (t & 15) << 2;
            *(float4*)&Ws[kk][cc] = *(const float4*)(w_out + (size_t)(k0 + kk) * 256 + c0 + cc);
            *(float4*)&Ys[kk][cc] = *(const float4*)(Y + (size_t)(k0 + kk) * N_TOK + n0 + cc);
        }
        __syncthreads();
        #pragma unroll
        for (int kk = 0; kk < 16; kk++) {
            float av[4], bv[4];
            *(float4*)av = *(const float4*)&Ws[kk][ty * 4];
            *(float4*)bv = *(const float4*)&Ys[kk][tx * 4];
            #pragma unroll
            for (int i = 0; i < 4; i++)
                #pragma unroll
                for (int j = 0; j < 4; j++)
                    acc[i][j] = fmaf(av[i], bv[j], acc[i][j]);
        }
        __syncthreads();
    }

    #pragma unroll
    for (int i = 0; i < 4; i++) {
        int c = c0 + ty * 4 + i;
        float bb = b_out[c];
        size_t off = ((size_t)b * CH + c) * N_TOK + n0 + tx * 4;
        float4 xv = *(const float4*)(x + off);
        float4 v = make_float4(acc[i][0] + bb + xv.x, acc[i][1] + bb + xv.y,
                               acc[i][2] + bb + xv.z, acc[i][3] + bb + xv.w);
        *(float4*)(out + off) = v;
    }
}

// ---------------------------------------------------------------------------
extern "C" void kernel_launch(void* const* d_in, const int* in_sizes, int n_in,
                              void* d_out, int out_size) {
    const float* x       = (const float*)d_in[0];
    const float* w_embed = (const float*)d_in[1];
    const float* b_embed = (const float*)d_in[2];
    const float* w_out   = (const float*)d_in[3];
    const float* b_out   = (const float*)d_in[4];
    float* out = (float*)d_out;

    qkv_kernel<<<dim3(64, 3, 8), 256>>>(x, w_embed, b_embed);

    const int smem = (4 * 4096 + 192) * (int)sizeof(float);   // 66304 B
    cudaFuncSetAttribute(attn_kernel, cudaFuncAttributeMaxDynamicSharedMemorySize, smem);
    attn_kernel<<<dim3(64, 8), 256, smem>>>();

    proj_kernel<<<dim3(64, 4, 2), 256>>>(x, w_out, b_out, out);
}